// round 9
// baseline (speedup 1.0000x reference)
#include <cuda_runtime.h>
#include <cuda_fp16.h>
#include <cstdint>

#define NLVL  10
#define EMB   64
#define NROWS 10002   // 2 zero rows + 10000 table rows

__device__ __align__(16)  float  g_ew[12];             // exp(w[l]); [10],[11]=0
__device__ __align__(256) __half g_tab[NROWS * EMB];   // fp16 concept_emb_cat, row=128B

// Convert table fp32->fp16 (rows shifted by +2, rows 0/1 zeroed) and exp(w).
__global__ void conv_kernel(const float* __restrict__ emb,
                            const float* __restrict__ w, int n4) {
    const int tid = blockIdx.x * blockDim.x + threadIdx.x;
    if (blockIdx.x == 0) {
        if (threadIdx.x < 12)
            g_ew[threadIdx.x] = (threadIdx.x < NLVL) ? __expf(w[threadIdx.x]) : 0.0f;
        if (threadIdx.x < 16)   // zero rows 0,1: 256B = 16 x 16B
            reinterpret_cast<uint4*>(g_tab)[threadIdx.x] = make_uint4(0u,0u,0u,0u);
    }
    if (tid < n4) {
        const float4 v = *reinterpret_cast<const float4*>(emb + (size_t)tid * 4);
        const __half2 h0 = __floats2half2_rn(v.x, v.y);
        const __half2 h1 = __floats2half2_rn(v.z, v.w);
        uint2 p;
        p.x = *reinterpret_cast<const unsigned*>(&h0);
        p.y = *reinterpret_cast<const unsigned*>(&h1);
        *reinterpret_cast<uint2*>(g_tab + 2 * EMB + (size_t)tid * 4) = p;
    }
}

// 16 lanes per token (lane hl covers cols [4*hl, 4*hl+4) = 8B of fp16).
// Gathers via cp.async.ca 8B into per-warp smem (no scoreboard); 128-thread
// CTAs with high residency for latency hiding. Warps self-contained.
__global__ __launch_bounds__(128, 12) void kcroute_kernel(
    const int* __restrict__ croutes,   // [ntok, NLVL]
    float*     __restrict__ out,       // [ntok, EMB]
    int ntok)
{
    // [warp][token-in-warp][level][64 halves] : 2.5 KB/warp, 10 KB/block
    __shared__ __half stab[4][2][NLVL][EMB];

    const int tid  = threadIdx.x;
    const int wid  = tid >> 5;
    const int half = (tid >> 4) & 1;     // token within warp
    const int hl   = tid & 15;           // 8B slice within the 128B row
    int tok = blockIdx.x * 8 + (tid >> 4);
    const bool valid = (tok < ntok);
    if (!valid) tok = 0;                 // clamp: loads safe, store guarded

    // Indices: 5x LDG.64, broadcast within the half-warp.
    const int2* cr = reinterpret_cast<const int2*>(croutes + (size_t)tok * NLVL);
    const int2 i0 = __ldg(cr + 0), i1 = __ldg(cr + 1), i2 = __ldg(cr + 2),
               i3 = __ldg(cr + 3), i4 = __ldg(cr + 4);
    const int idx[NLVL] = { i0.x, i0.y, i1.x, i1.y, i2.x, i2.y,
                            i3.x, i3.y, i4.x, i4.y };

    // Issue all 10 row-slice copies (8B each) via cp.async.
    uint32_t sbase;
    {
        const void* p0 = &stab[wid][half][0][hl * 4];
        asm("{ .reg .u64 t; cvta.to.shared.u64 t, %1; cvt.u32.u64 %0, t; }"
            : "=r"(sbase) : "l"(p0));
    }
#pragma unroll
    for (int l = 0; l < NLVL; l++) {
        const __half* gp = g_tab + ((size_t)(idx[l] + 2)) * EMB + hl * 4;
        asm volatile("cp.async.ca.shared.global [%0], [%1], 8;"
                     :: "r"(sbase + l * (EMB * 2)), "l"(gp));
    }
    asm volatile("cp.async.commit_group;");

    // Softmax denominator while the copies are in flight.
    const float4 ea = *reinterpret_cast<const float4*>(&g_ew[0]);
    const float4 eb = *reinterpret_cast<const float4*>(&g_ew[4]);
    const float2 ec = *reinterpret_cast<const float2*>(&g_ew[8]);
    const float e[NLVL] = { ea.x, ea.y, ea.z, ea.w,
                            eb.x, eb.y, eb.z, eb.w, ec.x, ec.y };
    float s = 0.0f;
#pragma unroll
    for (int l = 0; l < NLVL; l++) s += (idx[l] != -2) ? e[l] : 0.0f;
    const float inv = (s > 0.0f) ? __frcp_rn(s) : 0.0f;

    asm volatile("cp.async.wait_group 0;");
    __syncwarp();

    // Packed f32x2 accumulation: 2 FFMA2 per level.
    unsigned long long acc0 = 0ull, acc1 = 0ull;
#pragma unroll
    for (int l = 0; l < NLVL; l++) {
        const uint2 v = *reinterpret_cast<const uint2*>(&stab[wid][half][l][hl * 4]);
        const float2 a = __half22float2(*reinterpret_cast<const __half2*>(&v.x));
        const float2 b = __half22float2(*reinterpret_cast<const __half2*>(&v.y));
        unsigned long long va, vb, ev;
        asm("mov.b64 %0, {%1, %2};" : "=l"(va) : "f"(a.x), "f"(a.y));
        asm("mov.b64 %0, {%1, %2};" : "=l"(vb) : "f"(b.x), "f"(b.y));
        asm("mov.b64 %0, {%1, %1};" : "=l"(ev) : "r"(__float_as_uint(e[l])));
        asm("fma.rn.f32x2 %0, %1, %2, %0;" : "+l"(acc0) : "l"(va), "l"(ev));
        asm("fma.rn.f32x2 %0, %1, %2, %0;" : "+l"(acc1) : "l"(vb), "l"(ev));
    }
    unsigned long long iv, o0, o1;
    asm("mov.b64 %0, {%1, %1};" : "=l"(iv) : "r"(__float_as_uint(inv)));
    asm("mul.rn.f32x2 %0, %1, %2;" : "=l"(o0) : "l"(acc0), "l"(iv));
    asm("mul.rn.f32x2 %0, %1, %2;" : "=l"(o1) : "l"(acc1), "l"(iv));

    if (valid) {
        float4 o;
        asm("mov.b64 {%0, %1}, %2;" : "=f"(o.x), "=f"(o.y) : "l"(o0));
        asm("mov.b64 {%0, %1}, %2;" : "=f"(o.z), "=f"(o.w) : "l"(o1));
        *reinterpret_cast<float4*>(&out[(size_t)tok * EMB + hl * 4]) = o;
    }
}

extern "C" void kernel_launch(void* const* d_in, const int* in_sizes, int n_in,
                              void* d_out, int out_size) {
    const int*   croutes = (const int*)d_in[0];
    // d_in[1] (tailcs) unused by the reference computation.
    const float* emb     = (const float*)d_in[2];
    const float* w       = (const float*)d_in[3];
    float*       out     = (float*)d_out;

    const int ntok = in_sizes[1];                 // B * S
    const int n4   = in_sizes[2] / 4;             // table float4 chunks
    conv_kernel<<<(n4 + 511) / 512, 512>>>(emb, w, n4);

    const int blocks = (ntok + 7) / 8;            // 8 tokens per 128-thread block
    kcroute_kernel<<<blocks, 128>>>(croutes, out, ntok);
}

// round 10
// speedup vs baseline: 1.1404x; 1.1404x over previous
#include <cuda_runtime.h>
#include <cuda_fp16.h>
#include <cstdint>

#define NLVL  10
#define EMB   64
#define NROWS 10002   // 2 zero rows + 10000 table rows

__device__ __align__(16)  float  g_ew[12];             // exp(w[l]); [10],[11]=0
__device__ __align__(256) __half g_tab[NROWS * EMB];   // fp16 concept_emb_cat, row=128B

// Convert table fp32->fp16 (rows shifted by +2, rows 0/1 zeroed) and exp(w).
__global__ void conv_kernel(const float* __restrict__ emb,
                            const float* __restrict__ w, int n4) {
    const int tid = blockIdx.x * blockDim.x + threadIdx.x;
    if (blockIdx.x == 0) {
        if (threadIdx.x < 12)
            g_ew[threadIdx.x] = (threadIdx.x < NLVL) ? __expf(w[threadIdx.x]) : 0.0f;
        if (threadIdx.x < 16)   // zero rows 0,1: 256B = 16 x 16B
            reinterpret_cast<uint4*>(g_tab)[threadIdx.x] = make_uint4(0u,0u,0u,0u);
    }
    if (tid < n4) {
        const float4 v = *reinterpret_cast<const float4*>(emb + (size_t)tid * 4);
        const __half2 h0 = __floats2half2_rn(v.x, v.y);
        const __half2 h1 = __floats2half2_rn(v.z, v.w);
        uint2 p;
        p.x = *reinterpret_cast<const unsigned*>(&h0);
        p.y = *reinterpret_cast<const unsigned*>(&h1);
        *reinterpret_cast<uint2*>(g_tab + 2 * EMB + (size_t)tid * 4) = p;
    }
}

// 8 lanes per token (lane qi covers cols [8*qi, 8*qi+8) = 16B of fp16).
// Gathers via cp.async.cg (16B, L2-direct) into per-warp smem, split into two
// commit groups so compute on levels 0-4 overlaps arrival of levels 5-9.
// Warps self-contained (no block barriers). 5 CTAs/SM for residency.
__global__ __launch_bounds__(256, 5) void kcroute_kernel(
    const int* __restrict__ croutes,   // [ntok, NLVL]
    float*     __restrict__ out,       // [ntok, EMB]
    int ntok)
{
    // [warp][token-in-warp][level][64 halves] : 5 KB/warp, 40 KB/block
    __shared__ __half stab[8][4][NLVL][EMB];

    const int tid = threadIdx.x;
    const int wid = tid >> 5;
    const int tw  = (tid >> 3) & 3;      // token within warp (0..3)
    const int qi  = tid & 7;             // 16B slice within the 128B row
    int tok = blockIdx.x * 32 + (tid >> 3);
    const bool valid = (tok < ntok);
    if (!valid) tok = 0;                 // clamp: loads safe, store guarded

    // Indices: 5x LDG.64, broadcast within the 8-lane group.
    const int2* cr = reinterpret_cast<const int2*>(croutes + (size_t)tok * NLVL);
    const int2 i0 = __ldg(cr + 0), i1 = __ldg(cr + 1), i2 = __ldg(cr + 2),
               i3 = __ldg(cr + 3), i4 = __ldg(cr + 4);
    const int idx[NLVL] = { i0.x, i0.y, i1.x, i1.y, i2.x, i2.y,
                            i3.x, i3.y, i4.x, i4.y };

    uint32_t sbase;
    {
        const void* p0 = &stab[wid][tw][0][qi * 8];
        asm("{ .reg .u64 t; cvta.to.shared.u64 t, %1; cvt.u32.u64 %0, t; }"
            : "=r"(sbase) : "l"(p0));
    }
    // Group A: levels 0-4.
#pragma unroll
    for (int l = 0; l < 5; l++) {
        const __half* gp = g_tab + ((size_t)(idx[l] + 2)) * EMB + qi * 8;
        asm volatile("cp.async.cg.shared.global [%0], [%1], 16;"
                     :: "r"(sbase + l * (EMB * 2)), "l"(gp));
    }
    asm volatile("cp.async.commit_group;");
    // Group B: levels 5-9.
#pragma unroll
    for (int l = 5; l < NLVL; l++) {
        const __half* gp = g_tab + ((size_t)(idx[l] + 2)) * EMB + qi * 8;
        asm volatile("cp.async.cg.shared.global [%0], [%1], 16;"
                     :: "r"(sbase + l * (EMB * 2)), "l"(gp));
    }
    asm volatile("cp.async.commit_group;");

    // Softmax denominator while copies are in flight.
    const float4 ea = *reinterpret_cast<const float4*>(&g_ew[0]);
    const float4 eb = *reinterpret_cast<const float4*>(&g_ew[4]);
    const float2 ec = *reinterpret_cast<const float2*>(&g_ew[8]);
    const float e[NLVL] = { ea.x, ea.y, ea.z, ea.w,
                            eb.x, eb.y, eb.z, eb.w, ec.x, ec.y };
    float s = 0.0f;
#pragma unroll
    for (int l = 0; l < NLVL; l++) s += (idx[l] != -2) ? e[l] : 0.0f;
    const float inv = (s > 0.0f) ? __frcp_rn(s) : 0.0f;

    float acc[8] = {0.f,0.f,0.f,0.f,0.f,0.f,0.f,0.f};

    // Wait for group A only (group B may still be in flight), compute levels 0-4.
    asm volatile("cp.async.wait_group 1;");
    __syncwarp();
#pragma unroll
    for (int l = 0; l < 5; l++) {
        const uint4 v = *reinterpret_cast<const uint4*>(&stab[wid][tw][l][qi * 8]);
        const float2 a = __half22float2(*reinterpret_cast<const __half2*>(&v.x));
        const float2 b = __half22float2(*reinterpret_cast<const __half2*>(&v.y));
        const float2 c = __half22float2(*reinterpret_cast<const __half2*>(&v.z));
        const float2 d = __half22float2(*reinterpret_cast<const __half2*>(&v.w));
        acc[0] = fmaf(e[l], a.x, acc[0]);
        acc[1] = fmaf(e[l], a.y, acc[1]);
        acc[2] = fmaf(e[l], b.x, acc[2]);
        acc[3] = fmaf(e[l], b.y, acc[3]);
        acc[4] = fmaf(e[l], c.x, acc[4]);
        acc[5] = fmaf(e[l], c.y, acc[5]);
        acc[6] = fmaf(e[l], d.x, acc[6]);
        acc[7] = fmaf(e[l], d.y, acc[7]);
    }

    // Wait for group B, compute levels 5-9.
    asm volatile("cp.async.wait_group 0;");
    __syncwarp();
#pragma unroll
    for (int l = 5; l < NLVL; l++) {
        const uint4 v = *reinterpret_cast<const uint4*>(&stab[wid][tw][l][qi * 8]);
        const float2 a = __half22float2(*reinterpret_cast<const __half2*>(&v.x));
        const float2 b = __half22float2(*reinterpret_cast<const __half2*>(&v.y));
        const float2 c = __half22float2(*reinterpret_cast<const __half2*>(&v.z));
        const float2 d = __half22float2(*reinterpret_cast<const __half2*>(&v.w));
        acc[0] = fmaf(e[l], a.x, acc[0]);
        acc[1] = fmaf(e[l], a.y, acc[1]);
        acc[2] = fmaf(e[l], b.x, acc[2]);
        acc[3] = fmaf(e[l], b.y, acc[3]);
        acc[4] = fmaf(e[l], c.x, acc[4]);
        acc[5] = fmaf(e[l], c.y, acc[5]);
        acc[6] = fmaf(e[l], d.x, acc[6]);
        acc[7] = fmaf(e[l], d.y, acc[7]);
    }

    if (valid) {
        float* op = out + (size_t)tok * EMB + qi * 8;
        *reinterpret_cast<float4*>(op) =
            make_float4(acc[0]*inv, acc[1]*inv, acc[2]*inv, acc[3]*inv);
        *reinterpret_cast<float4*>(op + 4) =
            make_float4(acc[4]*inv, acc[5]*inv, acc[6]*inv, acc[7]*inv);
    }
}

extern "C" void kernel_launch(void* const* d_in, const int* in_sizes, int n_in,
                              void* d_out, int out_size) {
    const int*   croutes = (const int*)d_in[0];
    // d_in[1] (tailcs) unused by the reference computation.
    const float* emb     = (const float*)d_in[2];
    const float* w       = (const float*)d_in[3];
    float*       out     = (float*)d_out;

    const int ntok = in_sizes[1];                 // B * S
    const int n4   = in_sizes[2] / 4;             // table float4 chunks
    conv_kernel<<<(n4 + 255) / 256, 256>>>(emb, w, n4);

    const int blocks = (ntok + 31) / 32;          // 32 tokens per block
    kcroute_kernel<<<blocks, 256>>>(croutes, out, ntok);
}